// round 13
// baseline (speedup 1.0000x reference)
#include <cuda_runtime.h>
#include <cuda_fp16.h>
#include <cstdint>

// Problem constants
#define Bn  2
#define Tn  2048
#define En  1024
#define NHn 16
#define HSn 64
#define Mn  (Bn * Tn)        // 4096 token rows

// ---------------- scratch (device globals; no allocation) ----------------
__device__ __half g_Xh[(size_t)Mn * En];
__device__ __half g_Wqh[(size_t)En * En];
__device__ __half g_Wkh[(size_t)En * En];
__device__ __half g_Wvh[(size_t)En * En];
__device__ __half g_Woh[(size_t)En * En];
__device__ __half g_Qh[(size_t)Mn * En];   // pre-scaled by 1/8
__device__ __half g_Kh[(size_t)Mn * En];
__device__ __half g_Vh[(size_t)Mn * En];
__device__ __half g_Ah[(size_t)Mn * En];

// =====================================================================
// Baseline-PTX helpers
// =====================================================================
__device__ __forceinline__ uint32_t smem_u32(const void* p) {
    uint32_t a;
    asm("{ .reg .u64 t; cvta.to.shared.u64 t, %1; cvt.u32.u64 %0, t; }"
        : "=r"(a) : "l"(p));
    return a;
}

__device__ __forceinline__ void mma_f16(float* d, const uint32_t* a,
                                        const uint32_t* b) {
    asm volatile(
        "mma.sync.aligned.m16n8k16.row.col.f32.f16.f16.f32 "
        "{%0,%1,%2,%3}, {%4,%5,%6,%7}, {%8,%9}, {%0,%1,%2,%3};\n"
        : "+f"(d[0]), "+f"(d[1]), "+f"(d[2]), "+f"(d[3])
        : "r"(a[0]), "r"(a[1]), "r"(a[2]), "r"(a[3]), "r"(b[0]), "r"(b[1]));
}

__device__ __forceinline__ void ldsm_x4(uint32_t* r, uint32_t a) {
    asm volatile("ldmatrix.sync.aligned.m8n8.x4.shared.b16 {%0,%1,%2,%3}, [%4];"
                 : "=r"(r[0]), "=r"(r[1]), "=r"(r[2]), "=r"(r[3]) : "r"(a));
}
__device__ __forceinline__ void ldsm_x4_t(uint32_t* r, uint32_t a) {
    asm volatile("ldmatrix.sync.aligned.m8n8.x4.trans.shared.b16 {%0,%1,%2,%3}, [%4];"
                 : "=r"(r[0]), "=r"(r[1]), "=r"(r[2]), "=r"(r[3]) : "r"(a));
}

__device__ __forceinline__ void cp16(uint32_t d, const void* g) {
    asm volatile("cp.async.cg.shared.global [%0], [%1], 16;" :: "r"(d), "l"(g));
}
#define CP_COMMIT() asm volatile("cp.async.commit_group;" ::: "memory")
#define CP_WAIT0()  asm volatile("cp.async.wait_group 0;" ::: "memory")
#define CP_WAIT1()  asm volatile("cp.async.wait_group 1;" ::: "memory")

__device__ __forceinline__ uint32_t pack2f(float a, float b) {
    __half2 t = __floats2half2_rn(a, b);     // single F2FP.PACK
    return *reinterpret_cast<uint32_t*>(&t);
}

// packed fp16 2^x
__device__ __forceinline__ uint32_t h2exp2u(uint32_t x) {
    uint32_t r;
    asm("ex2.approx.f16x2 %0, %1;" : "=r"(r) : "r"(x));
    return r;
}

// =====================================================================
// Fused split kernel: X + all weights -> fp16.
// =====================================================================
__global__ void __launch_bounds__(256) split_all(
    const float* __restrict__ X,  const float* __restrict__ Wq,
    const float* __restrict__ Wk, const float* __restrict__ Wv,
    const float* __restrict__ Wo)
{
    const int i = blockIdx.x * blockDim.x + threadIdx.x;   // float4 index
    const float* src; __half* hi; int base;
    if (i < (1 << 20)) {
        src = X; hi = g_Xh; base = i;
    } else {
        const int r = i - (1 << 20);
        const int seg = r >> 18;
        base = r & ((1 << 18) - 1);
        switch (seg) {
            case 0:  src = Wq; hi = g_Wqh; break;
            case 1:  src = Wk; hi = g_Wkh; break;
            case 2:  src = Wv; hi = g_Wvh; break;
            default: src = Wo; hi = g_Woh; break;
        }
    }
    const float4 v = *(const float4*)(src + (size_t)base * 4);
    uint2 hh;
    hh.x = pack2f(v.x, v.y);
    hh.y = pack2f(v.z, v.w);
    *(uint2*)(hi + (size_t)base * 4) = hh;
}

// =====================================================================
// GEMM: C[(64*MI)x128] = A * B^T + bias, fp16 mma.sync, K-stage 64.
// Templated M-tile: MI=1 (64 rows, finer load-balance) or MI=2 (128).
// 256 thr, 8 warps (4m x 2n), cp.async triple buffer, 16 stages.
// smem row = 64 fp16 + 16B pad = 144B.
// =====================================================================
#define GROW   144
#define GTILE_B (128 * GROW)           // B tile: 18432
#define NSTAGES (En / 64)              // 16

// per-MI sizes
#define GTILE_A(MI)  (64 * (MI) * GROW)
#define GSTAGE(MI)   (GTILE_A(MI) + GTILE_B)
#define GEMM_SMEM(MI) (3 * GSTAGE(MI))  // MI=1: 82944, MI=2: 110592

template <int MI>
__device__ __forceinline__ void gemm_prefetch(
    uint32_t sbs, const __half* pA0, const __half* pB0, int k0, int tid)
{
    const int NA = 64 * MI * 8;            // # of A cp16 ops
    #pragma unroll
    for (int i = 0; i < (64 * MI + 128) * 8 / 256; i++) {
        const int cc = i * 256 + tid;
        if (cc < NA) {
            const int row = cc >> 3, seg = cc & 7;
            cp16(sbs + row * GROW + seg * 16,
                 pA0 + (size_t)row * En + k0 + seg * 8);
        } else {
            const int r = cc - NA;
            const int row = r >> 3, seg = r & 7;
            cp16(sbs + GTILE_A(MI) + row * GROW + seg * 16,
                 pB0 + (size_t)row * En + k0 + seg * 8);
        }
    }
}

template <int MI>
__device__ __forceinline__ void gemm_core(
    const __half* __restrict__ Ah, const __half* __restrict__ Bh,
    const float* __restrict__ bias, float* __restrict__ outF,
    __half* __restrict__ outH, float outScale)
{
    extern __shared__ char smc[];
    const uint32_t sb = smem_u32(smc);
    const int tid = threadIdx.x, lane = tid & 31, wid = tid >> 5;
    const int wm = wid & 3, wn = wid >> 2;
    const int rowBase = blockIdx.y * 64 * MI, colBase = blockIdx.x * 128;

    const __half* pA0 = Ah + (size_t)rowBase * En;
    const __half* pB0 = Bh + (size_t)colBase * En;

    float acc[MI][8][4];
    #pragma unroll
    for (int i = 0; i < MI; i++)
        #pragma unroll
        for (int j = 0; j < 8; j++)
            #pragma unroll
            for (int e = 0; e < 4; e++) acc[i][j][e] = 0.f;

    gemm_prefetch<MI>(sb, pA0, pB0, 0, tid);
    CP_COMMIT();
    gemm_prefetch<MI>(sb + GSTAGE(MI), pA0, pB0, 64, tid);
    CP_COMMIT();

    const uint32_t aoff = (lane & 15) * GROW + (lane >> 4) * 16;
    const uint32_t boff = (((lane & 16) >> 1) + (lane & 7)) * GROW
                        + ((lane & 8) ? 16 : 0);

    uint32_t bufc = 0, bufp = 2;   // compute buf, prefetch buf (mod-3)
    for (int st = 0; st < NSTAGES; st++) {
        CP_WAIT1();          // stage st landed
        __syncthreads();     // all readers of buf[bufp] done
        if (st + 2 < NSTAGES) {
            gemm_prefetch<MI>(sb + bufp * GSTAGE(MI), pA0, pB0,
                              (st + 2) * 64, tid);
            CP_COMMIT();
        }
        const uint32_t s0 = sb + bufc * GSTAGE(MI);
        bufc = (bufc == 2) ? 0 : bufc + 1;
        bufp = (bufp == 2) ? 0 : bufp + 1;
        const uint32_t aH = s0, bH = s0 + GTILE_A(MI);

        #pragma unroll
        for (int kk = 0; kk < 4; kk++) {
            uint32_t ah[MI][4], bh4[4][4];
            #pragma unroll
            for (int mi = 0; mi < MI; mi++)
                ldsm_x4(ah[mi],
                        aH + (wm * 16 * MI + mi * 16) * GROW + aoff + kk * 32);
            #pragma unroll
            for (int n4 = 0; n4 < 4; n4++)
                ldsm_x4(bh4[n4], bH + (wn * 64 + n4 * 16) * GROW + boff + kk * 32);
            #pragma unroll
            for (int mi = 0; mi < MI; mi++)
                #pragma unroll
                for (int nj = 0; nj < 8; nj++)
                    mma_f16(acc[mi][nj], ah[mi], &bh4[nj >> 1][(nj & 1) * 2]);
        }
    }

    // epilogue
    #pragma unroll
    for (int mi = 0; mi < MI; mi++) {
        const int rb = rowBase + wm * 16 * MI + mi * 16 + (lane >> 2);
        #pragma unroll
        for (int half = 0; half < 2; half++) {
            const size_t r = (size_t)(rb + half * 8);
            #pragma unroll
            for (int nj = 0; nj < 8; nj++) {
                const int col = colBase + wn * 64 + nj * 8 + (lane & 3) * 2;
                float v0 = (acc[mi][nj][half * 2 + 0] + bias[col]) * outScale;
                float v1 = (acc[mi][nj][half * 2 + 1] + bias[col + 1]) * outScale;
                if (outF) {
                    *(float2*)&outF[r * En + col] = make_float2(v0, v1);
                } else {
                    *(uint32_t*)&outH[r * En + col] = pack2f(v0, v1);
                }
            }
        }
    }
}

// qkv: M-tile 64 (1536 tiles -> finer per-SM load balance)
__global__ void __launch_bounds__(256, 2) gemm_qkv(
    const float* bq, const float* bk, const float* bv)
{
    if (blockIdx.z == 0)
        gemm_core<1>(g_Xh, g_Wqh, bq, nullptr, g_Qh, 0.125f);
    else if (blockIdx.z == 1)
        gemm_core<1>(g_Xh, g_Wkh, bk, nullptr, g_Kh, 1.0f);
    else
        gemm_core<1>(g_Xh, g_Wvh, bv, nullptr, g_Vh, 1.0f);
}

// out-proj: M-tile 128 (no balance gain from halving; keep traffic low)
__global__ void __launch_bounds__(256, 2) gemm_out(const float* bo, float* out)
{
    gemm_core<2>(g_Ah, g_Woh, bo, out, nullptr, 1.0f);
}

// =====================================================================
// Flash attention (causal) via mma.sync fp16. Q pre-scaled by 1/8.
// S = Qh*Kh; P via ex2.approx.f16x2; l = P @ ones on tensor pipe.
// Warps 0-3 skip the fully-masked final diagonal k-tile.
// KV stage: 2 tiles [64x64] fp16, row 144B. Triple buffer. 2 CTAs/SM.
// =====================================================================
#define KVTILE  (64 * 144)     // 9216
#define KVSTAGE (2 * KVTILE)   // 18432
#define FL_SMEM (3 * KVSTAGE)  // 55296

__device__ __forceinline__ void kv_prefetch(
    uint32_t sbs, int kt2, const __half* Kh, const __half* Vh, int tid)
{
    const size_t rowoff = (size_t)kt2 * 64;
    #pragma unroll
    for (int t = 0; t < 2; t++) {
        const __half* src = (t == 0) ? Kh : Vh;
        #pragma unroll
        for (int i = 0; i < 2; i++) {
            int cc  = i * 256 + tid;     // 0..511
            int row = cc >> 3, seg = cc & 7;
            cp16(sbs + t * KVTILE + row * 144 + seg * 16,
                 src + (rowoff + row) * En + seg * 8);
        }
    }
}

__global__ void __launch_bounds__(256, 2) flash_mma()
{
    extern __shared__ char smc[];
    const uint32_t sb = smem_u32(smc);
    const int tid = threadIdx.x, lane = tid & 31, wp = tid >> 5;
    const int g = lane >> 2, tg = lane & 3;
    const int qt = (int)gridDim.x - 1 - (int)blockIdx.x;   // big tiles first
    const int bh = blockIdx.y, bb = bh >> 4, hh = bh & 15;

    const size_t headoff = (size_t)bb * Tn * En + hh * HSn;
    const __half* Kh = g_Kh + headoff;
    const __half* Vh = g_Vh + headoff;

    const int nk = 2 * (qt + 1);   // always >= 2

    kv_prefetch(sb, 0, Kh, Vh, tid);
    CP_COMMIT();
    kv_prefetch(sb + KVSTAGE, 1, Kh, Vh, tid);
    CP_COMMIT();

    // Q fragments (fp16), loaded straight from gmem in frag layout
    uint32_t qh[4][4];
    {
        const size_t q0 = (size_t)(bb * Tn + qt * 128 + wp * 16 + g) * En
                        + hh * HSn;
        const size_t q1 = q0 + (size_t)8 * En;
        #pragma unroll
        for (int kk = 0; kk < 4; kk++) {
            const int c0 = kk * 16 + tg * 2, c1 = c0 + 8;
            qh[kk][0] = *(const uint32_t*)&g_Qh[q0 + c0];
            qh[kk][1] = *(const uint32_t*)&g_Qh[q1 + c0];
            qh[kk][2] = *(const uint32_t*)&g_Qh[q0 + c1];
            qh[kk][3] = *(const uint32_t*)&g_Qh[q1 + c1];
        }
    }

    float o[8][4];
    #pragma unroll
    for (int i = 0; i < 8; i++)
        #pragma unroll
        for (int e = 0; e < 4; e++) o[i][e] = 0.f;
    float la[4] = {0.f, 0.f, 0.f, 0.f};     // l accumulator (P @ ones)
    float m0 = -1e30f, m1 = -1e30f;
    const int qrow0 = qt * 128 + wp * 16 + g, qrow1 = qrow0 + 8;

    const uint32_t kboff = (((lane & 16) >> 1) + (lane & 7)) * 144
                         + ((lane & 8) ? 16 : 0);
    const float L2E = 1.4426950408889634f;
    const uint32_t onesb[2] = {0x3C003C00u, 0x3C003C00u};   // half2(1,1) x2

    uint32_t bufc = 0, bufp = 2;
    for (int kt = 0; kt < nk; kt++) {
        CP_WAIT1();
        __syncthreads();
        if (kt + 2 < nk) {
            kv_prefetch(sb + bufp * KVSTAGE, kt + 2, Kh, Vh, tid);
            CP_COMMIT();
        }
        const uint32_t s0 = sb + bufc * KVSTAGE;
        bufc = (bufc == 2) ? 0 : bufc + 1;
        bufp = (bufp == 2) ? 0 : bufp + 1;
        const uint32_t kmh = s0, vmh = s0 + KVTILE;

        // warps 0-3: final diagonal k-tile is fully masked (keys all
        // exceed their q rows) -> skip all compute (no barriers inside)
        if (kt == nk - 1 && wp < 4) continue;

        // ---- S = Qh Kh^T, 8 n8-tiles of 64 keys
        float s[8][4];
        #pragma unroll
        for (int i = 0; i < 8; i++)
            #pragma unroll
            for (int e = 0; e < 4; e++) s[i][e] = 0.f;

        #pragma unroll
        for (int kk = 0; kk < 4; kk++) {
            uint32_t kbh[4][4];
            #pragma unroll
            for (int n4 = 0; n4 < 4; n4++)
                ldsm_x4(kbh[n4], kmh + n4 * 16 * 144 + kboff + kk * 32);
            #pragma unroll
            for (int nj = 0; nj < 8; nj++)
                mma_f16(s[nj], qh[kk], &kbh[nj >> 1][(nj & 1) * 2]);
        }

        // ---- causal mask (diagonal tiles only)
        if (kt * 64 + 63 > qrow0) {
            #pragma unroll
            for (int nj = 0; nj < 8; nj++)
                #pragma unroll
                for (int e = 0; e < 4; e++) {
                    const int key = kt * 64 + nj * 8 + tg * 2 + (e & 1);
                    const int qr  = (e < 2) ? qrow0 : qrow1;
                    if (key > qr) s[nj][e] = -1e30f;
                }
        }

        // ---- row max (rows g and g+8)
        float mx0 = -1e30f, mx1 = -1e30f;
        #pragma unroll
        for (int nj = 0; nj < 8; nj++) {
            mx0 = fmaxf(mx0, fmaxf(s[nj][0], s[nj][1]));
            mx1 = fmaxf(mx1, fmaxf(s[nj][2], s[nj][3]));
        }
        mx0 = fmaxf(mx0, __shfl_xor_sync(0xffffffffu, mx0, 1));
        mx0 = fmaxf(mx0, __shfl_xor_sync(0xffffffffu, mx0, 2));
        mx1 = fmaxf(mx1, __shfl_xor_sync(0xffffffffu, mx1, 1));
        mx1 = fmaxf(mx1, __shfl_xor_sync(0xffffffffu, mx1, 2));
        const float mn0 = fmaxf(m0, mx0), mn1 = fmaxf(m1, mx1);

        // ---- rescale o, la only if some lane's max changed (warp-uniform)
        if (__any_sync(0xffffffffu, (mn0 > m0) || (mn1 > m1))) {
            const float a0 = __expf(m0 - mn0), a1 = __expf(m1 - mn1);
            la[0] *= a0; la[2] *= a1;
            #pragma unroll
            for (int nj = 0; nj < 8; nj++) {
                o[nj][0] *= a0; o[nj][1] *= a0;
                o[nj][2] *= a1; o[nj][3] *= a1;
            }
        }
        m0 = mn0; m1 = mn1;

        // ---- P = 2^((s-m)*log2e) in packed fp16 (feeds PV directly)
        const float nb0 = -mn0 * L2E, nb1 = -mn1 * L2E;
        uint32_t ph[8][2];
        #pragma unroll
        for (int nj = 0; nj < 8; nj++) {
            ph[nj][0] = h2exp2u(pack2f(fmaf(s[nj][0], L2E, nb0),
                                       fmaf(s[nj][1], L2E, nb0)));
            ph[nj][1] = h2exp2u(pack2f(fmaf(s[nj][2], L2E, nb1),
                                       fmaf(s[nj][3], L2E, nb1)));
        }

        // ---- O += Ph Vh;  la += Ph @ ones (row sums on tensor pipe)
        #pragma unroll
        for (int kk = 0; kk < 4; kk++) {
            uint32_t pah[4];
            pah[0] = ph[2 * kk][0];
            pah[1] = ph[2 * kk][1];
            pah[2] = ph[2 * kk + 1][0];
            pah[3] = ph[2 * kk + 1][1];
            mma_f16(la, pah, onesb);           // row-sum MMA
            uint32_t vbh[4][4];
            const uint32_t voff = (kk * 16 + (lane & 15)) * 144
                                + ((lane & 16) ? 16 : 0);
            #pragma unroll
            for (int nb = 0; nb < 4; nb++)
                ldsm_x4_t(vbh[nb], vmh + voff + nb * 32);
            #pragma unroll
            for (int nd = 0; nd < 8; nd++)
                mma_f16(o[nd], pah, &vbh[nd >> 1][(nd & 1) * 2]);
        }
    }

    // ---- epilogue: normalize, fp16 store into g_Ah
    const float i0 = 1.f / la[0], i1 = 1.f / la[2];
    const size_t r0 = (size_t)(bb * Tn + qrow0) * En + hh * HSn;
    const size_t r1 = r0 + (size_t)8 * En;
    #pragma unroll
    for (int nd = 0; nd < 8; nd++) {
        const int col = nd * 8 + tg * 2;
        *(uint32_t*)&g_Ah[r0 + col] = pack2f(o[nd][0] * i0, o[nd][1] * i0);
        *(uint32_t*)&g_Ah[r1 + col] = pack2f(o[nd][2] * i1, o[nd][3] * i1);
    }
}

// =====================================================================
extern "C" void kernel_launch(void* const* d_in, const int* in_sizes, int n_in,
                              void* d_out, int out_size)
{
    (void)in_sizes; (void)n_in; (void)out_size;
    const float* X  = (const float*)d_in[0];
    const float* Wq = (const float*)d_in[1];
    const float* bq = (const float*)d_in[2];
    const float* Wk = (const float*)d_in[3];
    const float* bk = (const float*)d_in[4];
    const float* Wv = (const float*)d_in[5];
    const float* bv = (const float*)d_in[6];
    const float* Wo = (const float*)d_in[7];
    const float* bo = (const float*)d_in[8];
    float* out = (float*)d_out;

    cudaFuncSetAttribute(gemm_qkv,
                         cudaFuncAttributeMaxDynamicSharedMemorySize,
                         GEMM_SMEM(1));
    cudaFuncSetAttribute(gemm_out,
                         cudaFuncAttributeMaxDynamicSharedMemorySize,
                         GEMM_SMEM(2));
    cudaFuncSetAttribute(flash_mma,
                         cudaFuncAttributeMaxDynamicSharedMemorySize, FL_SMEM);

    dim3 blk(256);
    split_all<<<8192, 256>>>(X, Wq, Wk, Wv, Wo);
    gemm_qkv<<<dim3(En / 128, Mn / 64, 3), blk, GEMM_SMEM(1)>>>(bq, bk, bv);
    flash_mma<<<dim3(Tn / 128, Bn * NHn), blk, FL_SMEM>>>();
    gemm_out<<<dim3(En / 128, Mn / 128), blk, GEMM_SMEM(2)>>>(bo, out);
}

// round 14
// speedup vs baseline: 1.0980x; 1.0980x over previous
#include <cuda_runtime.h>
#include <cuda_fp16.h>
#include <cstdint>

// Problem constants
#define Bn  2
#define Tn  2048
#define En  1024
#define NHn 16
#define HSn 64
#define Mn  (Bn * Tn)        // 4096 token rows

// ---------------- scratch (device globals; no allocation) ----------------
__device__ __half g_Xh[(size_t)Mn * En];
__device__ __half g_Wqh[(size_t)En * En];
__device__ __half g_Wkh[(size_t)En * En];
__device__ __half g_Wvh[(size_t)En * En];
__device__ __half g_Woh[(size_t)En * En];
__device__ __half g_Qh[(size_t)Mn * En];   // pre-scaled by 1/8
__device__ __half g_Kh[(size_t)Mn * En];
__device__ __half g_Vh[(size_t)Mn * En];
__device__ __half g_Ah[(size_t)Mn * En];

// =====================================================================
// Baseline-PTX helpers
// =====================================================================
__device__ __forceinline__ uint32_t smem_u32(const void* p) {
    uint32_t a;
    asm("{ .reg .u64 t; cvta.to.shared.u64 t, %1; cvt.u32.u64 %0, t; }"
        : "=r"(a) : "l"(p));
    return a;
}

__device__ __forceinline__ void mma_f16(float* d, const uint32_t* a,
                                        const uint32_t* b) {
    asm volatile(
        "mma.sync.aligned.m16n8k16.row.col.f32.f16.f16.f32 "
        "{%0,%1,%2,%3}, {%4,%5,%6,%7}, {%8,%9}, {%0,%1,%2,%3};\n"
        : "+f"(d[0]), "+f"(d[1]), "+f"(d[2]), "+f"(d[3])
        : "r"(a[0]), "r"(a[1]), "r"(a[2]), "r"(a[3]), "r"(b[0]), "r"(b[1]));
}

__device__ __forceinline__ void ldsm_x4(uint32_t* r, uint32_t a) {
    asm volatile("ldmatrix.sync.aligned.m8n8.x4.shared.b16 {%0,%1,%2,%3}, [%4];"
                 : "=r"(r[0]), "=r"(r[1]), "=r"(r[2]), "=r"(r[3]) : "r"(a));
}
__device__ __forceinline__ void ldsm_x4_t(uint32_t* r, uint32_t a) {
    asm volatile("ldmatrix.sync.aligned.m8n8.x4.trans.shared.b16 {%0,%1,%2,%3}, [%4];"
                 : "=r"(r[0]), "=r"(r[1]), "=r"(r[2]), "=r"(r[3]) : "r"(a));
}

__device__ __forceinline__ void cp16(uint32_t d, const void* g) {
    asm volatile("cp.async.cg.shared.global [%0], [%1], 16;" :: "r"(d), "l"(g));
}
#define CP_COMMIT() asm volatile("cp.async.commit_group;" ::: "memory")
#define CP_WAIT0()  asm volatile("cp.async.wait_group 0;" ::: "memory")
#define CP_WAIT1()  asm volatile("cp.async.wait_group 1;" ::: "memory")

__device__ __forceinline__ uint32_t pack2f(float a, float b) {
    __half2 t = __floats2half2_rn(a, b);     // single F2FP.PACK
    return *reinterpret_cast<uint32_t*>(&t);
}

// packed fp16 2^x
__device__ __forceinline__ uint32_t h2exp2u(uint32_t x) {
    uint32_t r;
    asm("ex2.approx.f16x2 %0, %1;" : "=r"(r) : "r"(x));
    return r;
}

// =====================================================================
// Fused split kernel: X + all weights -> fp16.
// =====================================================================
__global__ void __launch_bounds__(256) split_all(
    const float* __restrict__ X,  const float* __restrict__ Wq,
    const float* __restrict__ Wk, const float* __restrict__ Wv,
    const float* __restrict__ Wo)
{
    const int i = blockIdx.x * blockDim.x + threadIdx.x;   // float4 index
    const float* src; __half* hi; int base;
    if (i < (1 << 20)) {
        src = X; hi = g_Xh; base = i;
    } else {
        const int r = i - (1 << 20);
        const int seg = r >> 18;
        base = r & ((1 << 18) - 1);
        switch (seg) {
            case 0:  src = Wq; hi = g_Wqh; break;
            case 1:  src = Wk; hi = g_Wkh; break;
            case 2:  src = Wv; hi = g_Wvh; break;
            default: src = Wo; hi = g_Woh; break;
        }
    }
    const float4 v = *(const float4*)(src + (size_t)base * 4);
    uint2 hh;
    hh.x = pack2f(v.x, v.y);
    hh.y = pack2f(v.z, v.w);
    *(uint2*)(hi + (size_t)base * 4) = hh;
}

// =====================================================================
// GEMM: C[128x128] = A * B^T + bias, fp16 mma.sync, K-stage 64.
// (R12 config — M64 experiment reverted: smaller tiles double LDSM/sync
//  overhead per MMA; (4m x 2n) is the LDSM-minimal warp layout.)
// 256 thr, 8 warps, cp.async triple buffer, 16 stages, 1 sync/stage.
// =====================================================================
#define GROW   144
#define GTILE  (128 * GROW)    // 18432: one [128 x 64] fp16 tile
#define GSTAGE (2 * GTILE)     // A, B = 36864
#define GEMM_SMEM (3 * GSTAGE) // 110592
#define NSTAGES (En / 64)      // 16

__device__ __forceinline__ void gemm_prefetch(
    uint32_t sbs, const __half* pA0, const __half* pB0, int k0, int tid)
{
    #pragma unroll
    for (int t = 0; t < 2; t++) {
        const __half* s = (t == 0) ? pA0 : pB0;
        #pragma unroll
        for (int i = 0; i < 4; i++) {
            int cc  = i * 256 + tid;       // 0..1023
            int row = cc >> 3, seg = cc & 7;
            cp16(sbs + t * GTILE + row * GROW + seg * 16,
                 s + (size_t)row * En + k0 + seg * 8);
        }
    }
}

__device__ __forceinline__ void gemm_core(
    const __half* __restrict__ Ah, const __half* __restrict__ Bh,
    const float* __restrict__ bias, float* __restrict__ outF,
    __half* __restrict__ outH, float outScale)
{
    extern __shared__ char smc[];
    const uint32_t sb = smem_u32(smc);
    const int tid = threadIdx.x, lane = tid & 31, wid = tid >> 5;
    const int wm = wid & 3, wn = wid >> 2;
    const int rowBase = blockIdx.y * 128, colBase = blockIdx.x * 128;

    const __half* pA0 = Ah + (size_t)rowBase * En;
    const __half* pB0 = Bh + (size_t)colBase * En;

    float acc[2][8][4];
    #pragma unroll
    for (int i = 0; i < 2; i++)
        #pragma unroll
        for (int j = 0; j < 8; j++)
            #pragma unroll
            for (int e = 0; e < 4; e++) acc[i][j][e] = 0.f;

    gemm_prefetch(sb, pA0, pB0, 0, tid);
    CP_COMMIT();
    gemm_prefetch(sb + GSTAGE, pA0, pB0, 64, tid);
    CP_COMMIT();

    const uint32_t aoff = (lane & 15) * GROW + (lane >> 4) * 16;
    const uint32_t boff = (((lane & 16) >> 1) + (lane & 7)) * GROW
                        + ((lane & 8) ? 16 : 0);

    uint32_t bufc = 0, bufp = 2;   // compute buf, prefetch buf (mod-3)
    for (int st = 0; st < NSTAGES; st++) {
        CP_WAIT1();          // stage st landed
        __syncthreads();     // all readers of buf[bufp] done
        if (st + 2 < NSTAGES) {
            gemm_prefetch(sb + bufp * GSTAGE, pA0, pB0, (st + 2) * 64, tid);
            CP_COMMIT();
        }
        const uint32_t s0 = sb + bufc * GSTAGE;
        bufc = (bufc == 2) ? 0 : bufc + 1;
        bufp = (bufp == 2) ? 0 : bufp + 1;
        const uint32_t aH = s0, bH = s0 + GTILE;

        #pragma unroll
        for (int kk = 0; kk < 4; kk++) {
            uint32_t ah[2][4], bh4[4][4];
            #pragma unroll
            for (int mi = 0; mi < 2; mi++)
                ldsm_x4(ah[mi], aH + (wm * 32 + mi * 16) * GROW + aoff + kk * 32);
            #pragma unroll
            for (int n4 = 0; n4 < 4; n4++)
                ldsm_x4(bh4[n4], bH + (wn * 64 + n4 * 16) * GROW + boff + kk * 32);
            #pragma unroll
            for (int mi = 0; mi < 2; mi++)
                #pragma unroll
                for (int nj = 0; nj < 8; nj++)
                    mma_f16(acc[mi][nj], ah[mi], &bh4[nj >> 1][(nj & 1) * 2]);
        }
    }

    // epilogue
    #pragma unroll
    for (int mi = 0; mi < 2; mi++) {
        const int rb = rowBase + wm * 32 + mi * 16 + (lane >> 2);
        #pragma unroll
        for (int half = 0; half < 2; half++) {
            const size_t r = (size_t)(rb + half * 8);
            #pragma unroll
            for (int nj = 0; nj < 8; nj++) {
                const int col = colBase + wn * 64 + nj * 8 + (lane & 3) * 2;
                float v0 = (acc[mi][nj][half * 2 + 0] + bias[col]) * outScale;
                float v1 = (acc[mi][nj][half * 2 + 1] + bias[col + 1]) * outScale;
                if (outF) {
                    *(float2*)&outF[r * En + col] = make_float2(v0, v1);
                } else {
                    *(uint32_t*)&outH[r * En + col] = pack2f(v0, v1);
                }
            }
        }
    }
}

__global__ void __launch_bounds__(256, 2) gemm_qkv(
    const float* bq, const float* bk, const float* bv)
{
    if (blockIdx.z == 0)
        gemm_core(g_Xh, g_Wqh, bq, nullptr, g_Qh, 0.125f);
    else if (blockIdx.z == 1)
        gemm_core(g_Xh, g_Wkh, bk, nullptr, g_Kh, 1.0f);
    else
        gemm_core(g_Xh, g_Wvh, bv, nullptr, g_Vh, 1.0f);
}

__global__ void __launch_bounds__(256, 2) gemm_out(const float* bo, float* out)
{
    gemm_core(g_Ah, g_Woh, bo, out, nullptr, 1.0f);
}

// =====================================================================
// Flash attention (causal) via mma.sync fp16. Q pre-scaled by 1/8.
// S = Qh*Kh; P via ex2.approx.f16x2; l = P @ ones on tensor pipe.
// Causal skips: (a) warps 0-3 skip the fully-masked final diagonal tile;
// (b) per-warp n8-tile S-MMA skip + k16-chunk PV skip on diagonal tiles.
// KV stage: 2 tiles [64x64] fp16, row 144B. Triple buffer. 2 CTAs/SM.
// =====================================================================
#define KVTILE  (64 * 144)     // 9216
#define KVSTAGE (2 * KVTILE)   // 18432
#define FL_SMEM (3 * KVSTAGE)  // 55296

__device__ __forceinline__ void kv_prefetch(
    uint32_t sbs, int kt2, const __half* Kh, const __half* Vh, int tid)
{
    const size_t rowoff = (size_t)kt2 * 64;
    #pragma unroll
    for (int t = 0; t < 2; t++) {
        const __half* src = (t == 0) ? Kh : Vh;
        #pragma unroll
        for (int i = 0; i < 2; i++) {
            int cc  = i * 256 + tid;     // 0..511
            int row = cc >> 3, seg = cc & 7;
            cp16(sbs + t * KVTILE + row * 144 + seg * 16,
                 src + (rowoff + row) * En + seg * 8);
        }
    }
}

__global__ void __launch_bounds__(256, 2) flash_mma()
{
    extern __shared__ char smc[];
    const uint32_t sb = smem_u32(smc);
    const int tid = threadIdx.x, lane = tid & 31, wp = tid >> 5;
    const int g = lane >> 2, tg = lane & 3;
    const int qt = (int)gridDim.x - 1 - (int)blockIdx.x;   // big tiles first
    const int bh = blockIdx.y, bb = bh >> 4, hh = bh & 15;

    const size_t headoff = (size_t)bb * Tn * En + hh * HSn;
    const __half* Kh = g_Kh + headoff;
    const __half* Vh = g_Vh + headoff;

    const int nk = 2 * (qt + 1);   // always >= 2

    kv_prefetch(sb, 0, Kh, Vh, tid);
    CP_COMMIT();
    kv_prefetch(sb + KVSTAGE, 1, Kh, Vh, tid);
    CP_COMMIT();

    // Q fragments (fp16), loaded straight from gmem in frag layout
    uint32_t qh[4][4];
    {
        const size_t q0 = (size_t)(bb * Tn + qt * 128 + wp * 16 + g) * En
                        + hh * HSn;
        const size_t q1 = q0 + (size_t)8 * En;
        #pragma unroll
        for (int kk = 0; kk < 4; kk++) {
            const int c0 = kk * 16 + tg * 2, c1 = c0 + 8;
            qh[kk][0] = *(const uint32_t*)&g_Qh[q0 + c0];
            qh[kk][1] = *(const uint32_t*)&g_Qh[q1 + c0];
            qh[kk][2] = *(const uint32_t*)&g_Qh[q0 + c1];
            qh[kk][3] = *(const uint32_t*)&g_Qh[q1 + c1];
        }
    }

    float o[8][4];
    #pragma unroll
    for (int i = 0; i < 8; i++)
        #pragma unroll
        for (int e = 0; e < 4; e++) o[i][e] = 0.f;
    float la[4] = {0.f, 0.f, 0.f, 0.f};     // l accumulator (P @ ones)
    float m0 = -1e30f, m1 = -1e30f;
    const int qrow0 = qt * 128 + wp * 16 + g, qrow1 = qrow0 + 8;
    const int wmax  = qt * 128 + wp * 16 + 15;   // warp's max q row

    const uint32_t kboff = (((lane & 16) >> 1) + (lane & 7)) * 144
                         + ((lane & 8) ? 16 : 0);
    const float L2E = 1.4426950408889634f;
    const uint32_t onesb[2] = {0x3C003C00u, 0x3C003C00u};   // half2(1,1) x2

    uint32_t bufc = 0, bufp = 2;
    for (int kt = 0; kt < nk; kt++) {
        CP_WAIT1();
        __syncthreads();
        if (kt + 2 < nk) {
            kv_prefetch(sb + bufp * KVSTAGE, kt + 2, Kh, Vh, tid);
            CP_COMMIT();
        }
        const uint32_t s0 = sb + bufc * KVSTAGE;
        bufc = (bufc == 2) ? 0 : bufc + 1;
        bufp = (bufp == 2) ? 0 : bufp + 1;
        const uint32_t kmh = s0, vmh = s0 + KVTILE;
        const int kbase = kt * 64;

        // fully-masked tile for this warp -> skip all compute
        if (kbase > wmax) continue;

        // ---- S = Qh Kh^T, 8 n8-tiles of 64 keys (skip fully-masked tiles)
        float s[8][4];
        #pragma unroll
        for (int i = 0; i < 8; i++)
            #pragma unroll
            for (int e = 0; e < 4; e++) s[i][e] = 0.f;

        #pragma unroll
        for (int kk = 0; kk < 4; kk++) {
            uint32_t kbh[4][4];
            #pragma unroll
            for (int n4 = 0; n4 < 4; n4++)
                ldsm_x4(kbh[n4], kmh + n4 * 16 * 144 + kboff + kk * 32);
            #pragma unroll
            for (int nj = 0; nj < 8; nj++)
                if (kbase + nj * 8 <= wmax)
                    mma_f16(s[nj], qh[kk], &kbh[nj >> 1][(nj & 1) * 2]);
        }

        // ---- causal mask (diagonal tiles only; also zeroes skipped tiles)
        if (kbase + 63 > qrow0) {
            #pragma unroll
            for (int nj = 0; nj < 8; nj++)
                #pragma unroll
                for (int e = 0; e < 4; e++) {
                    const int key = kbase + nj * 8 + tg * 2 + (e & 1);
                    const int qr  = (e < 2) ? qrow0 : qrow1;
                    if (key > qr) s[nj][e] = -1e30f;
                }
        }

        // ---- row max (rows g and g+8)
        float mx0 = -1e30f, mx1 = -1e30f;
        #pragma unroll
        for (int nj = 0; nj < 8; nj++) {
            mx0 = fmaxf(mx0, fmaxf(s[nj][0], s[nj][1]));
            mx1 = fmaxf(mx1, fmaxf(s[nj][2], s[nj][3]));
        }
        mx0 = fmaxf(mx0, __shfl_xor_sync(0xffffffffu, mx0, 1));
        mx0 = fmaxf(mx0, __shfl_xor_sync(0xffffffffu, mx0, 2));
        mx1 = fmaxf(mx1, __shfl_xor_sync(0xffffffffu, mx1, 1));
        mx1 = fmaxf(mx1, __shfl_xor_sync(0xffffffffu, mx1, 2));
        const float mn0 = fmaxf(m0, mx0), mn1 = fmaxf(m1, mx1);

        // ---- rescale o, la only if some lane's max changed (warp-uniform)
        if (__any_sync(0xffffffffu, (mn0 > m0) || (mn1 > m1))) {
            const float a0 = __expf(m0 - mn0), a1 = __expf(m1 - mn1);
            la[0] *= a0; la[2] *= a1;
            #pragma unroll
            for (int nj = 0; nj < 8; nj++) {
                o[nj][0] *= a0; o[nj][1] *= a0;
                o[nj][2] *= a1; o[nj][3] *= a1;
            }
        }
        m0 = mn0; m1 = mn1;

        // ---- P = 2^((s-m)*log2e) in packed fp16 (feeds PV directly)
        const float nb0 = -mn0 * L2E, nb1 = -mn1 * L2E;
        uint32_t ph[8][2];
        #pragma unroll
        for (int nj = 0; nj < 8; nj++) {
            ph[nj][0] = h2exp2u(pack2f(fmaf(s[nj][0], L2E, nb0),
                                       fmaf(s[nj][1], L2E, nb0)));
            ph[nj][1] = h2exp2u(pack2f(fmaf(s[nj][2], L2E, nb1),
                                       fmaf(s[nj][3], L2E, nb1)));
        }

        // ---- O += Ph Vh;  la += Ph @ ones (skip fully-masked k16 chunks)
        #pragma unroll
        for (int kk = 0; kk < 4; kk++) {
            if (kbase + kk * 16 > wmax) continue;   // P == 0 there
            uint32_t pah[4];
            pah[0] = ph[2 * kk][0];
            pah[1] = ph[2 * kk][1];
            pah[2] = ph[2 * kk + 1][0];
            pah[3] = ph[2 * kk + 1][1];
            mma_f16(la, pah, onesb);           // row-sum MMA
            uint32_t vbh[4][4];
            const uint32_t voff = (kk * 16 + (lane & 15)) * 144
                                + ((lane & 16) ? 16 : 0);
            #pragma unroll
            for (int nb = 0; nb < 4; nb++)
                ldsm_x4_t(vbh[nb], vmh + voff + nb * 32);
            #pragma unroll
            for (int nd = 0; nd < 8; nd++)
                mma_f16(o[nd], pah, &vbh[nd >> 1][(nd & 1) * 2]);
        }
    }

    // ---- epilogue: normalize, fp16 store into g_Ah
    const float i0 = 1.f / la[0], i1 = 1.f / la[2];
    const size_t r0 = (size_t)(bb * Tn + qrow0) * En + hh * HSn;
    const size_t r1 = r0 + (size_t)8 * En;
    #pragma unroll
    for (int nd = 0; nd < 8; nd++) {
        const int col = nd * 8 + tg * 2;
        *(uint32_t*)&g_Ah[r0 + col] = pack2f(o[nd][0] * i0, o[nd][1] * i0);
        *(uint32_t*)&g_Ah[r1 + col] = pack2f(o[nd][2] * i1, o[nd][3] * i1);
    }
}

// =====================================================================
extern "C" void kernel_launch(void* const* d_in, const int* in_sizes, int n_in,
                              void* d_out, int out_size)
{
    (void)in_sizes; (void)n_in; (void)out_size;
    const float* X  = (const float*)d_in[0];
    const float* Wq = (const float*)d_in[1];
    const float* bq = (const float*)d_in[2];
    const float* Wk = (const float*)d_in[3];
    const float* bk = (const float*)d_in[4];
    const float* Wv = (const float*)d_in[5];
    const float* bv = (const float*)d_in[6];
    const float* Wo = (const float*)d_in[7];
    const float* bo = (const float*)d_in[8];
    float* out = (float*)d_out;

    cudaFuncSetAttribute(gemm_qkv,
                         cudaFuncAttributeMaxDynamicSharedMemorySize, GEMM_SMEM);
    cudaFuncSetAttribute(gemm_out,
                         cudaFuncAttributeMaxDynamicSharedMemorySize, GEMM_SMEM);
    cudaFuncSetAttribute(flash_mma,
                         cudaFuncAttributeMaxDynamicSharedMemorySize, FL_SMEM);

    dim3 blk(256);
    split_all<<<8192, 256>>>(X, Wq, Wk, Wv, Wo);
    gemm_qkv<<<dim3(En / 128, Mn / 128, 3), blk, GEMM_SMEM>>>(bq, bk, bv);
    flash_mma<<<dim3(Tn / 128, Bn * NHn), blk, FL_SMEM>>>();
    gemm_out<<<dim3(En / 128, Mn / 128), blk, GEMM_SMEM>>>(bo, out);
}

// round 15
// speedup vs baseline: 1.1922x; 1.0858x over previous
#include <cuda_runtime.h>
#include <cuda_fp16.h>
#include <cstdint>

// Problem constants
#define Bn  2
#define Tn  2048
#define En  1024
#define NHn 16
#define HSn 64
#define Mn  (Bn * Tn)        // 4096 token rows

// ---------------- scratch (device globals; no allocation) ----------------
__device__ __half g_Xh[(size_t)Mn * En];
__device__ __half g_Wqh[(size_t)En * En];
__device__ __half g_Wkh[(size_t)En * En];
__device__ __half g_Wvh[(size_t)En * En];
__device__ __half g_Woh[(size_t)En * En];
__device__ __half g_Qh[(size_t)Mn * En];   // pre-scaled by 1/8
__device__ __half g_Kh[(size_t)Mn * En];
__device__ __half g_Vh[(size_t)Mn * En];
__device__ __half g_Ah[(size_t)Mn * En];

// =====================================================================
// Baseline-PTX helpers
// =====================================================================
__device__ __forceinline__ uint32_t smem_u32(const void* p) {
    uint32_t a;
    asm("{ .reg .u64 t; cvta.to.shared.u64 t, %1; cvt.u32.u64 %0, t; }"
        : "=r"(a) : "l"(p));
    return a;
}

__device__ __forceinline__ void mma_f16(float* d, const uint32_t* a,
                                        const uint32_t* b) {
    asm volatile(
        "mma.sync.aligned.m16n8k16.row.col.f32.f16.f16.f32 "
        "{%0,%1,%2,%3}, {%4,%5,%6,%7}, {%8,%9}, {%0,%1,%2,%3};\n"
        : "+f"(d[0]), "+f"(d[1]), "+f"(d[2]), "+f"(d[3])
        : "r"(a[0]), "r"(a[1]), "r"(a[2]), "r"(a[3]), "r"(b[0]), "r"(b[1]));
}

__device__ __forceinline__ void ldsm_x4(uint32_t* r, uint32_t a) {
    asm volatile("ldmatrix.sync.aligned.m8n8.x4.shared.b16 {%0,%1,%2,%3}, [%4];"
                 : "=r"(r[0]), "=r"(r[1]), "=r"(r[2]), "=r"(r[3]) : "r"(a));
}
__device__ __forceinline__ void ldsm_x4_t(uint32_t* r, uint32_t a) {
    asm volatile("ldmatrix.sync.aligned.m8n8.x4.trans.shared.b16 {%0,%1,%2,%3}, [%4];"
                 : "=r"(r[0]), "=r"(r[1]), "=r"(r[2]), "=r"(r[3]) : "r"(a));
}

__device__ __forceinline__ void cp16(uint32_t d, const void* g) {
    asm volatile("cp.async.cg.shared.global [%0], [%1], 16;" :: "r"(d), "l"(g));
}
#define CP_COMMIT() asm volatile("cp.async.commit_group;" ::: "memory")
#define CP_WAIT0()  asm volatile("cp.async.wait_group 0;" ::: "memory")
#define CP_WAIT1()  asm volatile("cp.async.wait_group 1;" ::: "memory")

__device__ __forceinline__ uint32_t pack2f(float a, float b) {
    __half2 t = __floats2half2_rn(a, b);     // single F2FP.PACK
    return *reinterpret_cast<uint32_t*>(&t);
}

// packed fp16 2^x
__device__ __forceinline__ uint32_t h2exp2u(uint32_t x) {
    uint32_t r;
    asm("ex2.approx.f16x2 %0, %1;" : "=r"(r) : "r"(x));
    return r;
}

// =====================================================================
// Fused split kernel: X + all weights -> fp16.
// =====================================================================
__global__ void __launch_bounds__(256) split_all(
    const float* __restrict__ X,  const float* __restrict__ Wq,
    const float* __restrict__ Wk, const float* __restrict__ Wv,
    const float* __restrict__ Wo)
{
    const int i = blockIdx.x * blockDim.x + threadIdx.x;   // float4 index
    const float* src; __half* hi; int base;
    if (i < (1 << 20)) {
        src = X; hi = g_Xh; base = i;
    } else {
        const int r = i - (1 << 20);
        const int seg = r >> 18;
        base = r & ((1 << 18) - 1);
        switch (seg) {
            case 0:  src = Wq; hi = g_Wqh; break;
            case 1:  src = Wk; hi = g_Wkh; break;
            case 2:  src = Wv; hi = g_Wvh; break;
            default: src = Wo; hi = g_Woh; break;
        }
    }
    const float4 v = *(const float4*)(src + (size_t)base * 4);
    uint2 hh;
    hh.x = pack2f(v.x, v.y);
    hh.y = pack2f(v.z, v.w);
    *(uint2*)(hi + (size_t)base * 4) = hh;
}

// =====================================================================
// GEMM: C[128x128] = A * B^T + bias, fp16 mma.sync, K-stage 64.
// 256 thr, 8 warps (4m x 2n), cp.async triple buffer, 16 stages,
// one __syncthreads per stage. smem row = 64 fp16 + 16B pad = 144B.
// (exact R12 config)
// =====================================================================
#define GROW   144
#define GTILE  (128 * GROW)    // 18432: one [128 x 64] fp16 tile
#define GSTAGE (2 * GTILE)     // A, B = 36864
#define GEMM_SMEM (3 * GSTAGE) // 110592
#define NSTAGES (En / 64)      // 16

__device__ __forceinline__ void gemm_prefetch(
    uint32_t sbs, const __half* pA0, const __half* pB0, int k0, int tid)
{
    #pragma unroll
    for (int t = 0; t < 2; t++) {
        const __half* s = (t == 0) ? pA0 : pB0;
        #pragma unroll
        for (int i = 0; i < 4; i++) {
            int cc  = i * 256 + tid;       // 0..1023
            int row = cc >> 3, seg = cc & 7;
            cp16(sbs + t * GTILE + row * GROW + seg * 16,
                 s + (size_t)row * En + k0 + seg * 8);
        }
    }
}

__device__ __forceinline__ void gemm_core(
    const __half* __restrict__ Ah, const __half* __restrict__ Bh,
    const float* __restrict__ bias, float* __restrict__ outF,
    __half* __restrict__ outH, float outScale)
{
    extern __shared__ char smc[];
    const uint32_t sb = smem_u32(smc);
    const int tid = threadIdx.x, lane = tid & 31, wid = tid >> 5;
    const int wm = wid & 3, wn = wid >> 2;
    const int rowBase = blockIdx.y * 128, colBase = blockIdx.x * 128;

    const __half* pA0 = Ah + (size_t)rowBase * En;
    const __half* pB0 = Bh + (size_t)colBase * En;

    float acc[2][8][4];
    #pragma unroll
    for (int i = 0; i < 2; i++)
        #pragma unroll
        for (int j = 0; j < 8; j++)
            #pragma unroll
            for (int e = 0; e < 4; e++) acc[i][j][e] = 0.f;

    gemm_prefetch(sb, pA0, pB0, 0, tid);
    CP_COMMIT();
    gemm_prefetch(sb + GSTAGE, pA0, pB0, 64, tid);
    CP_COMMIT();

    const uint32_t aoff = (lane & 15) * GROW + (lane >> 4) * 16;
    const uint32_t boff = (((lane & 16) >> 1) + (lane & 7)) * GROW
                        + ((lane & 8) ? 16 : 0);

    uint32_t bufc = 0, bufp = 2;   // compute buf, prefetch buf (mod-3)
    for (int st = 0; st < NSTAGES; st++) {
        CP_WAIT1();          // stage st landed
        __syncthreads();     // all readers of buf[bufp] done
        if (st + 2 < NSTAGES) {
            gemm_prefetch(sb + bufp * GSTAGE, pA0, pB0, (st + 2) * 64, tid);
            CP_COMMIT();
        }
        const uint32_t s0 = sb + bufc * GSTAGE;
        bufc = (bufc == 2) ? 0 : bufc + 1;
        bufp = (bufp == 2) ? 0 : bufp + 1;
        const uint32_t aH = s0, bH = s0 + GTILE;

        #pragma unroll
        for (int kk = 0; kk < 4; kk++) {
            uint32_t ah[2][4], bh4[4][4];
            #pragma unroll
            for (int mi = 0; mi < 2; mi++)
                ldsm_x4(ah[mi], aH + (wm * 32 + mi * 16) * GROW + aoff + kk * 32);
            #pragma unroll
            for (int n4 = 0; n4 < 4; n4++)
                ldsm_x4(bh4[n4], bH + (wn * 64 + n4 * 16) * GROW + boff + kk * 32);
            #pragma unroll
            for (int mi = 0; mi < 2; mi++)
                #pragma unroll
                for (int nj = 0; nj < 8; nj++)
                    mma_f16(acc[mi][nj], ah[mi], &bh4[nj >> 1][(nj & 1) * 2]);
        }
    }

    // epilogue
    #pragma unroll
    for (int mi = 0; mi < 2; mi++) {
        const int rb = rowBase + wm * 32 + mi * 16 + (lane >> 2);
        #pragma unroll
        for (int half = 0; half < 2; half++) {
            const size_t r = (size_t)(rb + half * 8);
            #pragma unroll
            for (int nj = 0; nj < 8; nj++) {
                const int col = colBase + wn * 64 + nj * 8 + (lane & 3) * 2;
                float v0 = (acc[mi][nj][half * 2 + 0] + bias[col]) * outScale;
                float v1 = (acc[mi][nj][half * 2 + 1] + bias[col + 1]) * outScale;
                if (outF) {
                    *(float2*)&outF[r * En + col] = make_float2(v0, v1);
                } else {
                    *(uint32_t*)&outH[r * En + col] = pack2f(v0, v1);
                }
            }
        }
    }
}

__global__ void __launch_bounds__(256, 2) gemm_qkv(
    const float* bq, const float* bk, const float* bv)
{
    if (blockIdx.z == 0)
        gemm_core(g_Xh, g_Wqh, bq, nullptr, g_Qh, 0.125f);
    else if (blockIdx.z == 1)
        gemm_core(g_Xh, g_Wkh, bk, nullptr, g_Kh, 1.0f);
    else
        gemm_core(g_Xh, g_Wvh, bv, nullptr, g_Vh, 1.0f);
}

__global__ void __launch_bounds__(256, 2) gemm_out(const float* bo, float* out)
{
    gemm_core(g_Ah, g_Woh, bo, out, nullptr, 1.0f);
}

// =====================================================================
// Flash attention (causal) via mma.sync fp16. Q pre-scaled by 1/8.
// S = Qh*Kh; P via ex2.approx.f16x2; l = P @ ones on tensor pipe.
// R12 body (no per-fragment skips). CTA pairing: each CTA processes
// q-tiles (15-bx) and (bx) sequentially -> every CTA does exactly 34
// key-tiles -> 256 equal CTAs, single perfectly-balanced wave.
// KV stage: 2 tiles [64x64] fp16, row 144B. Triple buffer. 2 CTAs/SM.
// =====================================================================
#define KVTILE  (64 * 144)     // 9216
#define KVSTAGE (2 * KVTILE)   // 18432
#define FL_SMEM (3 * KVSTAGE)  // 55296

__device__ __forceinline__ void kv_prefetch(
    uint32_t sbs, int kt2, const __half* Kh, const __half* Vh, int tid)
{
    const size_t rowoff = (size_t)kt2 * 64;
    #pragma unroll
    for (int t = 0; t < 2; t++) {
        const __half* src = (t == 0) ? Kh : Vh;
        #pragma unroll
        for (int i = 0; i < 2; i++) {
            int cc  = i * 256 + tid;     // 0..511
            int row = cc >> 3, seg = cc & 7;
            cp16(sbs + t * KVTILE + row * 144 + seg * 16,
                 src + (rowoff + row) * En + seg * 8);
        }
    }
}

__device__ __forceinline__ void flash_one(
    int qt, uint32_t sb, int tid, int lane, int wp, int g, int tg,
    int bb, int hh, const __half* Kh, const __half* Vh)
{
    const int nk = 2 * (qt + 1);   // always >= 2

    kv_prefetch(sb, 0, Kh, Vh, tid);
    CP_COMMIT();
    kv_prefetch(sb + KVSTAGE, 1, Kh, Vh, tid);
    CP_COMMIT();

    // Q fragments (fp16), loaded straight from gmem in frag layout
    uint32_t qh[4][4];
    {
        const size_t q0 = (size_t)(bb * Tn + qt * 128 + wp * 16 + g) * En
                        + hh * HSn;
        const size_t q1 = q0 + (size_t)8 * En;
        #pragma unroll
        for (int kk = 0; kk < 4; kk++) {
            const int c0 = kk * 16 + tg * 2, c1 = c0 + 8;
            qh[kk][0] = *(const uint32_t*)&g_Qh[q0 + c0];
            qh[kk][1] = *(const uint32_t*)&g_Qh[q1 + c0];
            qh[kk][2] = *(const uint32_t*)&g_Qh[q0 + c1];
            qh[kk][3] = *(const uint32_t*)&g_Qh[q1 + c1];
        }
    }

    float o[8][4];
    #pragma unroll
    for (int i = 0; i < 8; i++)
        #pragma unroll
        for (int e = 0; e < 4; e++) o[i][e] = 0.f;
    float la[4] = {0.f, 0.f, 0.f, 0.f};     // l accumulator (P @ ones)
    float m0 = -1e30f, m1 = -1e30f;
    const int qrow0 = qt * 128 + wp * 16 + g, qrow1 = qrow0 + 8;

    const uint32_t kboff = (((lane & 16) >> 1) + (lane & 7)) * 144
                         + ((lane & 8) ? 16 : 0);
    const float L2E = 1.4426950408889634f;
    const uint32_t onesb[2] = {0x3C003C00u, 0x3C003C00u};   // half2(1,1) x2

    uint32_t bufc = 0, bufp = 2;
    for (int kt = 0; kt < nk; kt++) {
        CP_WAIT1();
        __syncthreads();
        if (kt + 2 < nk) {
            kv_prefetch(sb + bufp * KVSTAGE, kt + 2, Kh, Vh, tid);
            CP_COMMIT();
        }
        const uint32_t s0 = sb + bufc * KVSTAGE;
        bufc = (bufc == 2) ? 0 : bufc + 1;
        bufp = (bufp == 2) ? 0 : bufp + 1;
        const uint32_t kmh = s0, vmh = s0 + KVTILE;

        // ---- S = Qh Kh^T, 8 n8-tiles of 64 keys
        float s[8][4];
        #pragma unroll
        for (int i = 0; i < 8; i++)
            #pragma unroll
            for (int e = 0; e < 4; e++) s[i][e] = 0.f;

        #pragma unroll
        for (int kk = 0; kk < 4; kk++) {
            uint32_t kbh[4][4];
            #pragma unroll
            for (int n4 = 0; n4 < 4; n4++)
                ldsm_x4(kbh[n4], kmh + n4 * 16 * 144 + kboff + kk * 32);
            #pragma unroll
            for (int nj = 0; nj < 8; nj++)
                mma_f16(s[nj], qh[kk], &kbh[nj >> 1][(nj & 1) * 2]);
        }

        // ---- causal mask (diagonal tiles only)
        if (kt * 64 + 63 > qrow0) {
            #pragma unroll
            for (int nj = 0; nj < 8; nj++)
                #pragma unroll
                for (int e = 0; e < 4; e++) {
                    const int key = kt * 64 + nj * 8 + tg * 2 + (e & 1);
                    const int qr  = (e < 2) ? qrow0 : qrow1;
                    if (key > qr) s[nj][e] = -1e30f;
                }
        }

        // ---- row max (rows g and g+8)
        float mx0 = -1e30f, mx1 = -1e30f;
        #pragma unroll
        for (int nj = 0; nj < 8; nj++) {
            mx0 = fmaxf(mx0, fmaxf(s[nj][0], s[nj][1]));
            mx1 = fmaxf(mx1, fmaxf(s[nj][2], s[nj][3]));
        }
        mx0 = fmaxf(mx0, __shfl_xor_sync(0xffffffffu, mx0, 1));
        mx0 = fmaxf(mx0, __shfl_xor_sync(0xffffffffu, mx0, 2));
        mx1 = fmaxf(mx1, __shfl_xor_sync(0xffffffffu, mx1, 1));
        mx1 = fmaxf(mx1, __shfl_xor_sync(0xffffffffu, mx1, 2));
        const float mn0 = fmaxf(m0, mx0), mn1 = fmaxf(m1, mx1);

        // ---- rescale o, la only if some lane's max changed (warp-uniform)
        if (__any_sync(0xffffffffu, (mn0 > m0) || (mn1 > m1))) {
            const float a0 = __expf(m0 - mn0), a1 = __expf(m1 - mn1);
            la[0] *= a0; la[2] *= a1;
            #pragma unroll
            for (int nj = 0; nj < 8; nj++) {
                o[nj][0] *= a0; o[nj][1] *= a0;
                o[nj][2] *= a1; o[nj][3] *= a1;
            }
        }
        m0 = mn0; m1 = mn1;

        // ---- P = 2^((s-m)*log2e) in packed fp16 (feeds PV directly)
        const float nb0 = -mn0 * L2E, nb1 = -mn1 * L2E;
        uint32_t ph[8][2];
        #pragma unroll
        for (int nj = 0; nj < 8; nj++) {
            ph[nj][0] = h2exp2u(pack2f(fmaf(s[nj][0], L2E, nb0),
                                       fmaf(s[nj][1], L2E, nb0)));
            ph[nj][1] = h2exp2u(pack2f(fmaf(s[nj][2], L2E, nb1),
                                       fmaf(s[nj][3], L2E, nb1)));
        }

        // ---- O += Ph Vh;  la += Ph @ ones (row sums on tensor pipe)
        #pragma unroll
        for (int kk = 0; kk < 4; kk++) {
            uint32_t pah[4];
            pah[0] = ph[2 * kk][0];
            pah[1] = ph[2 * kk][1];
            pah[2] = ph[2 * kk + 1][0];
            pah[3] = ph[2 * kk + 1][1];
            mma_f16(la, pah, onesb);           // row-sum MMA
            uint32_t vbh[4][4];
            const uint32_t voff = (kk * 16 + (lane & 15)) * 144
                                + ((lane & 16) ? 16 : 0);
            #pragma unroll
            for (int nb = 0; nb < 4; nb++)
                ldsm_x4_t(vbh[nb], vmh + voff + nb * 32);
            #pragma unroll
            for (int nd = 0; nd < 8; nd++)
                mma_f16(o[nd], pah, &vbh[nd >> 1][(nd & 1) * 2]);
        }
    }

    // ---- epilogue: normalize, fp16 store into g_Ah
    const float i0 = 1.f / la[0], i1 = 1.f / la[2];
    const size_t r0 = (size_t)(bb * Tn + qrow0) * En + hh * HSn;
    const size_t r1 = r0 + (size_t)8 * En;
    #pragma unroll
    for (int nd = 0; nd < 8; nd++) {
        const int col = nd * 8 + tg * 2;
        *(uint32_t*)&g_Ah[r0 + col] = pack2f(o[nd][0] * i0, o[nd][1] * i0);
        *(uint32_t*)&g_Ah[r1 + col] = pack2f(o[nd][2] * i1, o[nd][3] * i1);
    }
}

__global__ void __launch_bounds__(256, 2) flash_mma()
{
    extern __shared__ char smc[];
    const uint32_t sb = smem_u32(smc);
    const int tid = threadIdx.x, lane = tid & 31, wp = tid >> 5;
    const int g = lane >> 2, tg = lane & 3;
    const int bx = blockIdx.x;                 // 0..7
    const int bh = blockIdx.y, bb = bh >> 4, hh = bh & 15;

    const size_t headoff = (size_t)bb * Tn * En + hh * HSn;
    const __half* Kh = g_Kh + headoff;
    const __half* Vh = g_Vh + headoff;

    // segment 1: big tile (15-bx); segment 2: small tile (bx).
    flash_one(15 - bx, sb, tid, lane, wp, g, tg, bb, hh, Kh, Vh);
    __syncthreads();   // all smem reads of segment 1 done before reuse
    flash_one(bx,      sb, tid, lane, wp, g, tg, bb, hh, Kh, Vh);
}

// =====================================================================
extern "C" void kernel_launch(void* const* d_in, const int* in_sizes, int n_in,
                              void* d_out, int out_size)
{
    (void)in_sizes; (void)n_in; (void)out_size;
    const float* X  = (const float*)d_in[0];
    const float* Wq = (const float*)d_in[1];
    const float* bq = (const float*)d_in[2];
    const float* Wk = (const float*)d_in[3];
    const float* bk = (const float*)d_in[4];
    const float* Wv = (const float*)d_in[5];
    const float* bv = (const float*)d_in[6];
    const float* Wo = (const float*)d_in[7];
    const float* bo = (const float*)d_in[8];
    float* out = (float*)d_out;

    cudaFuncSetAttribute(gemm_qkv,
                         cudaFuncAttributeMaxDynamicSharedMemorySize, GEMM_SMEM);
    cudaFuncSetAttribute(gemm_out,
                         cudaFuncAttributeMaxDynamicSharedMemorySize, GEMM_SMEM);
    cudaFuncSetAttribute(flash_mma,
                         cudaFuncAttributeMaxDynamicSharedMemorySize, FL_SMEM);

    dim3 blk(256);
    split_all<<<8192, 256>>>(X, Wq, Wk, Wv, Wo);
    gemm_qkv<<<dim3(En / 128, Mn / 128, 3), blk, GEMM_SMEM>>>(bq, bk, bv);
    flash_mma<<<dim3(Tn / 256, Bn * NHn), blk, FL_SMEM>>>();
    gemm_out<<<dim3(En / 128, Mn / 128), blk, GEMM_SMEM>>>(bo, out);
}

// round 16
// speedup vs baseline: 1.2046x; 1.0104x over previous
#include <cuda_runtime.h>
#include <cuda_fp16.h>
#include <cstdint>

// Problem constants
#define Bn  2
#define Tn  2048
#define En  1024
#define NHn 16
#define HSn 64
#define Mn  (Bn * Tn)        // 4096 token rows

// ---------------- scratch (device globals; no allocation) ----------------
__device__ __half g_Xh[(size_t)Mn * En];
__device__ __half g_Wqh[(size_t)En * En];
__device__ __half g_Wkh[(size_t)En * En];
__device__ __half g_Wvh[(size_t)En * En];
__device__ __half g_Woh[(size_t)En * En];
__device__ __half g_Qh[(size_t)Mn * En];   // pre-scaled by 1/8
__device__ __half g_Kh[(size_t)Mn * En];
__device__ __half g_Vh[(size_t)Mn * En];
__device__ __half g_Ah[(size_t)Mn * En];

// =====================================================================
// Baseline-PTX helpers
// =====================================================================
__device__ __forceinline__ uint32_t smem_u32(const void* p) {
    uint32_t a;
    asm("{ .reg .u64 t; cvta.to.shared.u64 t, %1; cvt.u32.u64 %0, t; }"
        : "=r"(a) : "l"(p));
    return a;
}

__device__ __forceinline__ void mma_f16(float* d, const uint32_t* a,
                                        const uint32_t* b) {
    asm volatile(
        "mma.sync.aligned.m16n8k16.row.col.f32.f16.f16.f32 "
        "{%0,%1,%2,%3}, {%4,%5,%6,%7}, {%8,%9}, {%0,%1,%2,%3};\n"
        : "+f"(d[0]), "+f"(d[1]), "+f"(d[2]), "+f"(d[3])
        : "r"(a[0]), "r"(a[1]), "r"(a[2]), "r"(a[3]), "r"(b[0]), "r"(b[1]));
}

__device__ __forceinline__ void ldsm_x4(uint32_t* r, uint32_t a) {
    asm volatile("ldmatrix.sync.aligned.m8n8.x4.shared.b16 {%0,%1,%2,%3}, [%4];"
                 : "=r"(r[0]), "=r"(r[1]), "=r"(r[2]), "=r"(r[3]) : "r"(a));
}
__device__ __forceinline__ void ldsm_x4_t(uint32_t* r, uint32_t a) {
    asm volatile("ldmatrix.sync.aligned.m8n8.x4.trans.shared.b16 {%0,%1,%2,%3}, [%4];"
                 : "=r"(r[0]), "=r"(r[1]), "=r"(r[2]), "=r"(r[3]) : "r"(a));
}

__device__ __forceinline__ void cp16(uint32_t d, const void* g) {
    asm volatile("cp.async.cg.shared.global [%0], [%1], 16;" :: "r"(d), "l"(g));
}
#define CP_COMMIT() asm volatile("cp.async.commit_group;" ::: "memory")
#define CP_WAIT0()  asm volatile("cp.async.wait_group 0;" ::: "memory")
#define CP_WAIT1()  asm volatile("cp.async.wait_group 1;" ::: "memory")
#define CP_WAIT2()  asm volatile("cp.async.wait_group 2;" ::: "memory")

__device__ __forceinline__ uint32_t pack2f(float a, float b) {
    __half2 t = __floats2half2_rn(a, b);     // single F2FP.PACK
    return *reinterpret_cast<uint32_t*>(&t);
}

// packed fp16 2^x
__device__ __forceinline__ uint32_t h2exp2u(uint32_t x) {
    uint32_t r;
    asm("ex2.approx.f16x2 %0, %1;" : "=r"(r) : "r"(x));
    return r;
}

// =====================================================================
// Fused split kernel: X + all weights -> fp16. MLP=4: each thread
// converts 4 consecutive float4s (64B) for deep load pipelining.
// =====================================================================
__global__ void __launch_bounds__(256) split_all(
    const float* __restrict__ X,  const float* __restrict__ Wq,
    const float* __restrict__ Wk, const float* __restrict__ Wv,
    const float* __restrict__ Wo)
{
    const int t = blockIdx.x * blockDim.x + threadIdx.x;   // 64B-chunk index
    const int i0 = t * 4;                                  // first float4 idx
    const float* src; __half* hi; int base;
    if (i0 < (1 << 20)) {
        src = X; hi = g_Xh; base = i0;
    } else {
        const int r = i0 - (1 << 20);
        const int seg = r >> 18;
        base = r & ((1 << 18) - 1);
        switch (seg) {
            case 0:  src = Wq; hi = g_Wqh; break;
            case 1:  src = Wk; hi = g_Wkh; break;
            case 2:  src = Wv; hi = g_Wvh; break;
            default: src = Wo; hi = g_Woh; break;
        }
    }
    float4 v[4];
    #pragma unroll
    for (int j = 0; j < 4; j++)
        v[j] = *(const float4*)(src + (size_t)(base + j) * 4);
    #pragma unroll
    for (int j = 0; j < 4; j++) {
        uint2 hh;
        hh.x = pack2f(v[j].x, v[j].y);
        hh.y = pack2f(v[j].z, v[j].w);
        *(uint2*)(hi + (size_t)(base + j) * 4) = hh;
    }
}

// =====================================================================
// GEMM: C[128x128] = A * B^T + bias, fp16 mma.sync, K-stage 64.
// 256 thr, 8 warps (4m x 2n), cp.async triple buffer, 16 stages.
// Stage head: sync -> prefetch(st+2) -> wait (2/1/0 tail-correct):
// the next fetch is issued BEFORE waiting on the current stage.
// =====================================================================
#define GROW   144
#define GTILE  (128 * GROW)    // 18432: one [128 x 64] fp16 tile
#define GSTAGE (2 * GTILE)     // A, B = 36864
#define GEMM_SMEM (3 * GSTAGE) // 110592
#define NSTAGES (En / 64)      // 16

__device__ __forceinline__ void gemm_prefetch(
    uint32_t sbs, const __half* pA0, const __half* pB0, int k0, int tid)
{
    #pragma unroll
    for (int t = 0; t < 2; t++) {
        const __half* s = (t == 0) ? pA0 : pB0;
        #pragma unroll
        for (int i = 0; i < 4; i++) {
            int cc  = i * 256 + tid;       // 0..1023
            int row = cc >> 3, seg = cc & 7;
            cp16(sbs + t * GTILE + row * GROW + seg * 16,
                 s + (size_t)row * En + k0 + seg * 8);
        }
    }
}

__device__ __forceinline__ void gemm_core(
    const __half* __restrict__ Ah, const __half* __restrict__ Bh,
    const float* __restrict__ bias, float* __restrict__ outF,
    __half* __restrict__ outH, float outScale)
{
    extern __shared__ char smc[];
    const uint32_t sb = smem_u32(smc);
    const int tid = threadIdx.x, lane = tid & 31, wid = tid >> 5;
    const int wm = wid & 3, wn = wid >> 2;
    const int rowBase = blockIdx.y * 128, colBase = blockIdx.x * 128;

    const __half* pA0 = Ah + (size_t)rowBase * En;
    const __half* pB0 = Bh + (size_t)colBase * En;

    float acc[2][8][4];
    #pragma unroll
    for (int i = 0; i < 2; i++)
        #pragma unroll
        for (int j = 0; j < 8; j++)
            #pragma unroll
            for (int e = 0; e < 4; e++) acc[i][j][e] = 0.f;

    gemm_prefetch(sb, pA0, pB0, 0, tid);
    CP_COMMIT();
    gemm_prefetch(sb + GSTAGE, pA0, pB0, 64, tid);
    CP_COMMIT();

    const uint32_t aoff = (lane & 15) * GROW + (lane >> 4) * 16;
    const uint32_t boff = (((lane & 16) >> 1) + (lane & 7)) * GROW
                        + ((lane & 8) ? 16 : 0);

    uint32_t bufc = 0, bufp = 2;   // compute buf, prefetch buf (mod-3)
    for (int st = 0; st < NSTAGES; st++) {
        __syncthreads();     // all readers of buf[bufp] done
        if (st + 2 < NSTAGES) {
            gemm_prefetch(sb + bufp * GSTAGE, pA0, pB0, (st + 2) * 64, tid);
            CP_COMMIT();
            CP_WAIT2();      // outstanding {st, st+1, st+2} -> st landed
        } else if (st == NSTAGES - 2) {
            CP_WAIT1();      // outstanding {st, st+1}
        } else {
            CP_WAIT0();      // outstanding {st}
        }
        const uint32_t s0 = sb + bufc * GSTAGE;
        bufc = (bufc == 2) ? 0 : bufc + 1;
        bufp = (bufp == 2) ? 0 : bufp + 1;
        const uint32_t aH = s0, bH = s0 + GTILE;

        #pragma unroll
        for (int kk = 0; kk < 4; kk++) {
            uint32_t ah[2][4], bh4[4][4];
            #pragma unroll
            for (int mi = 0; mi < 2; mi++)
                ldsm_x4(ah[mi], aH + (wm * 32 + mi * 16) * GROW + aoff + kk * 32);
            #pragma unroll
            for (int n4 = 0; n4 < 4; n4++)
                ldsm_x4(bh4[n4], bH + (wn * 64 + n4 * 16) * GROW + boff + kk * 32);
            #pragma unroll
            for (int mi = 0; mi < 2; mi++)
                #pragma unroll
                for (int nj = 0; nj < 8; nj++)
                    mma_f16(acc[mi][nj], ah[mi], &bh4[nj >> 1][(nj & 1) * 2]);
        }
    }

    // epilogue
    #pragma unroll
    for (int mi = 0; mi < 2; mi++) {
        const int rb = rowBase + wm * 32 + mi * 16 + (lane >> 2);
        #pragma unroll
        for (int half = 0; half < 2; half++) {
            const size_t r = (size_t)(rb + half * 8);
            #pragma unroll
            for (int nj = 0; nj < 8; nj++) {
                const int col = colBase + wn * 64 + nj * 8 + (lane & 3) * 2;
                float v0 = (acc[mi][nj][half * 2 + 0] + bias[col]) * outScale;
                float v1 = (acc[mi][nj][half * 2 + 1] + bias[col + 1]) * outScale;
                if (outF) {
                    *(float2*)&outF[r * En + col] = make_float2(v0, v1);
                } else {
                    *(uint32_t*)&outH[r * En + col] = pack2f(v0, v1);
                }
            }
        }
    }
}

__global__ void __launch_bounds__(256, 2) gemm_qkv(
    const float* bq, const float* bk, const float* bv)
{
    if (blockIdx.z == 0)
        gemm_core(g_Xh, g_Wqh, bq, nullptr, g_Qh, 0.125f);
    else if (blockIdx.z == 1)
        gemm_core(g_Xh, g_Wkh, bk, nullptr, g_Kh, 1.0f);
    else
        gemm_core(g_Xh, g_Wvh, bv, nullptr, g_Vh, 1.0f);
}

__global__ void __launch_bounds__(256, 2) gemm_out(const float* bo, float* out)
{
    gemm_core(g_Ah, g_Woh, bo, out, nullptr, 1.0f);
}

// =====================================================================
// Flash attention (causal) via mma.sync fp16. Q pre-scaled by 1/8.
// S = Qh*Kh; P via ex2.approx.f16x2; l = P @ ones on tensor pipe.
// CTA pairing: q-tiles (15-bx, bx) -> 256 equal CTAs, one wave.
// Same sync->prefetch->wait reordering as the GEMMs.
// KV stage: 2 tiles [64x64] fp16, row 144B. Triple buffer. 2 CTAs/SM.
// =====================================================================
#define KVTILE  (64 * 144)     // 9216
#define KVSTAGE (2 * KVTILE)   // 18432
#define FL_SMEM (3 * KVSTAGE)  // 55296

__device__ __forceinline__ void kv_prefetch(
    uint32_t sbs, int kt2, const __half* Kh, const __half* Vh, int tid)
{
    const size_t rowoff = (size_t)kt2 * 64;
    #pragma unroll
    for (int t = 0; t < 2; t++) {
        const __half* src = (t == 0) ? Kh : Vh;
        #pragma unroll
        for (int i = 0; i < 2; i++) {
            int cc  = i * 256 + tid;     // 0..511
            int row = cc >> 3, seg = cc & 7;
            cp16(sbs + t * KVTILE + row * 144 + seg * 16,
                 src + (rowoff + row) * En + seg * 8);
        }
    }
}

__device__ __forceinline__ void flash_one(
    int qt, uint32_t sb, int tid, int lane, int wp, int g, int tg,
    int bb, int hh, const __half* Kh, const __half* Vh)
{
    const int nk = 2 * (qt + 1);   // always >= 2

    kv_prefetch(sb, 0, Kh, Vh, tid);
    CP_COMMIT();
    kv_prefetch(sb + KVSTAGE, 1, Kh, Vh, tid);
    CP_COMMIT();

    // Q fragments (fp16), loaded straight from gmem in frag layout
    uint32_t qh[4][4];
    {
        const size_t q0 = (size_t)(bb * Tn + qt * 128 + wp * 16 + g) * En
                        + hh * HSn;
        const size_t q1 = q0 + (size_t)8 * En;
        #pragma unroll
        for (int kk = 0; kk < 4; kk++) {
            const int c0 = kk * 16 + tg * 2, c1 = c0 + 8;
            qh[kk][0] = *(const uint32_t*)&g_Qh[q0 + c0];
            qh[kk][1] = *(const uint32_t*)&g_Qh[q1 + c0];
            qh[kk][2] = *(const uint32_t*)&g_Qh[q0 + c1];
            qh[kk][3] = *(const uint32_t*)&g_Qh[q1 + c1];
        }
    }

    float o[8][4];
    #pragma unroll
    for (int i = 0; i < 8; i++)
        #pragma unroll
        for (int e = 0; e < 4; e++) o[i][e] = 0.f;
    float la[4] = {0.f, 0.f, 0.f, 0.f};     // l accumulator (P @ ones)
    float m0 = -1e30f, m1 = -1e30f;
    const int qrow0 = qt * 128 + wp * 16 + g, qrow1 = qrow0 + 8;

    const uint32_t kboff = (((lane & 16) >> 1) + (lane & 7)) * 144
                         + ((lane & 8) ? 16 : 0);
    const float L2E = 1.4426950408889634f;
    const uint32_t onesb[2] = {0x3C003C00u, 0x3C003C00u};   // half2(1,1) x2

    uint32_t bufc = 0, bufp = 2;
    for (int kt = 0; kt < nk; kt++) {
        __syncthreads();
        if (kt + 2 < nk) {
            kv_prefetch(sb + bufp * KVSTAGE, kt + 2, Kh, Vh, tid);
            CP_COMMIT();
            CP_WAIT2();
        } else if (kt == nk - 2) {
            CP_WAIT1();
        } else {
            CP_WAIT0();
        }
        const uint32_t s0 = sb + bufc * KVSTAGE;
        bufc = (bufc == 2) ? 0 : bufc + 1;
        bufp = (bufp == 2) ? 0 : bufp + 1;
        const uint32_t kmh = s0, vmh = s0 + KVTILE;

        // ---- S = Qh Kh^T, 8 n8-tiles of 64 keys
        float s[8][4];
        #pragma unroll
        for (int i = 0; i < 8; i++)
            #pragma unroll
            for (int e = 0; e < 4; e++) s[i][e] = 0.f;

        #pragma unroll
        for (int kk = 0; kk < 4; kk++) {
            uint32_t kbh[4][4];
            #pragma unroll
            for (int n4 = 0; n4 < 4; n4++)
                ldsm_x4(kbh[n4], kmh + n4 * 16 * 144 + kboff + kk * 32);
            #pragma unroll
            for (int nj = 0; nj < 8; nj++)
                mma_f16(s[nj], qh[kk], &kbh[nj >> 1][(nj & 1) * 2]);
        }

        // ---- causal mask (diagonal tiles only)
        if (kt * 64 + 63 > qrow0) {
            #pragma unroll
            for (int nj = 0; nj < 8; nj++)
                #pragma unroll
                for (int e = 0; e < 4; e++) {
                    const int key = kt * 64 + nj * 8 + tg * 2 + (e & 1);
                    const int qr  = (e < 2) ? qrow0 : qrow1;
                    if (key > qr) s[nj][e] = -1e30f;
                }
        }

        // ---- row max (rows g and g+8)
        float mx0 = -1e30f, mx1 = -1e30f;
        #pragma unroll
        for (int nj = 0; nj < 8; nj++) {
            mx0 = fmaxf(mx0, fmaxf(s[nj][0], s[nj][1]));
            mx1 = fmaxf(mx1, fmaxf(s[nj][2], s[nj][3]));
        }
        mx0 = fmaxf(mx0, __shfl_xor_sync(0xffffffffu, mx0, 1));
        mx0 = fmaxf(mx0, __shfl_xor_sync(0xffffffffu, mx0, 2));
        mx1 = fmaxf(mx1, __shfl_xor_sync(0xffffffffu, mx1, 1));
        mx1 = fmaxf(mx1, __shfl_xor_sync(0xffffffffu, mx1, 2));
        const float mn0 = fmaxf(m0, mx0), mn1 = fmaxf(m1, mx1);

        // ---- rescale o, la only if some lane's max changed (warp-uniform)
        if (__any_sync(0xffffffffu, (mn0 > m0) || (mn1 > m1))) {
            const float a0 = __expf(m0 - mn0), a1 = __expf(m1 - mn1);
            la[0] *= a0; la[2] *= a1;
            #pragma unroll
            for (int nj = 0; nj < 8; nj++) {
                o[nj][0] *= a0; o[nj][1] *= a0;
                o[nj][2] *= a1; o[nj][3] *= a1;
            }
        }
        m0 = mn0; m1 = mn1;

        // ---- P = 2^((s-m)*log2e) in packed fp16 (feeds PV directly)
        const float nb0 = -mn0 * L2E, nb1 = -mn1 * L2E;
        uint32_t ph[8][2];
        #pragma unroll
        for (int nj = 0; nj < 8; nj++) {
            ph[nj][0] = h2exp2u(pack2f(fmaf(s[nj][0], L2E, nb0),
                                       fmaf(s[nj][1], L2E, nb0)));
            ph[nj][1] = h2exp2u(pack2f(fmaf(s[nj][2], L2E, nb1),
                                       fmaf(s[nj][3], L2E, nb1)));
        }

        // ---- O += Ph Vh;  la += Ph @ ones (row sums on tensor pipe)
        #pragma unroll
        for (int kk = 0; kk < 4; kk++) {
            uint32_t pah[4];
            pah[0] = ph[2 * kk][0];
            pah[1] = ph[2 * kk][1];
            pah[2] = ph[2 * kk + 1][0];
            pah[3] = ph[2 * kk + 1][1];
            mma_f16(la, pah, onesb);           // row-sum MMA
            uint32_t vbh[4][4];
            const uint32_t voff = (kk * 16 + (lane & 15)) * 144
                                + ((lane & 16) ? 16 : 0);
            #pragma unroll
            for (int nb = 0; nb < 4; nb++)
                ldsm_x4_t(vbh[nb], vmh + voff + nb * 32);
            #pragma unroll
            for (int nd = 0; nd < 8; nd++)
                mma_f16(o[nd], pah, &vbh[nd >> 1][(nd & 1) * 2]);
        }
    }

    // ---- epilogue: normalize, fp16 store into g_Ah
    const float i0 = 1.f / la[0], i1 = 1.f / la[2];
    const size_t r0 = (size_t)(bb * Tn + qrow0) * En + hh * HSn;
    const size_t r1 = r0 + (size_t)8 * En;
    #pragma unroll
    for (int nd = 0; nd < 8; nd++) {
        const int col = nd * 8 + tg * 2;
        *(uint32_t*)&g_Ah[r0 + col] = pack2f(o[nd][0] * i0, o[nd][1] * i0);
        *(uint32_t*)&g_Ah[r1 + col] = pack2f(o[nd][2] * i1, o[nd][3] * i1);
    }
}

__global__ void __launch_bounds__(256, 2) flash_mma()
{
    extern __shared__ char smc[];
    const uint32_t sb = smem_u32(smc);
    const int tid = threadIdx.x, lane = tid & 31, wp = tid >> 5;
    const int g = lane >> 2, tg = lane & 3;
    const int bx = blockIdx.x;                 // 0..7
    const int bh = blockIdx.y, bb = bh >> 4, hh = bh & 15;

    const size_t headoff = (size_t)bb * Tn * En + hh * HSn;
    const __half* Kh = g_Kh + headoff;
    const __half* Vh = g_Vh + headoff;

    // segment 1: big tile (15-bx); segment 2: small tile (bx).
    flash_one(15 - bx, sb, tid, lane, wp, g, tg, bb, hh, Kh, Vh);
    __syncthreads();   // all smem reads of segment 1 done before reuse
    flash_one(bx,      sb, tid, lane, wp, g, tg, bb, hh, Kh, Vh);
}

// =====================================================================
extern "C" void kernel_launch(void* const* d_in, const int* in_sizes, int n_in,
                              void* d_out, int out_size)
{
    (void)in_sizes; (void)n_in; (void)out_size;
    const float* X  = (const float*)d_in[0];
    const float* Wq = (const float*)d_in[1];
    const float* bq = (const float*)d_in[2];
    const float* Wk = (const float*)d_in[3];
    const float* bk = (const float*)d_in[4];
    const float* Wv = (const float*)d_in[5];
    const float* bv = (const float*)d_in[6];
    const float* Wo = (const float*)d_in[7];
    const float* bo = (const float*)d_in[8];
    float* out = (float*)d_out;

    cudaFuncSetAttribute(gemm_qkv,
                         cudaFuncAttributeMaxDynamicSharedMemorySize, GEMM_SMEM);
    cudaFuncSetAttribute(gemm_out,
                         cudaFuncAttributeMaxDynamicSharedMemorySize, GEMM_SMEM);
    cudaFuncSetAttribute(flash_mma,
                         cudaFuncAttributeMaxDynamicSharedMemorySize, FL_SMEM);

    dim3 blk(256);
    split_all<<<2048, 256>>>(X, Wq, Wk, Wv, Wo);
    gemm_qkv<<<dim3(En / 128, Mn / 128, 3), blk, GEMM_SMEM>>>(bq, bk, bv);
    flash_mma<<<dim3(Tn / 256, Bn * NHn), blk, FL_SMEM>>>();
    gemm_out<<<dim3(En / 128, Mn / 128), blk, GEMM_SMEM>>>(bo, out);
}